// round 11
// baseline (speedup 1.0000x reference)
#include <cuda_runtime.h>
#include <cuda_bf16.h>
#include <math.h>
#include <stdint.h>

#define N_NODES  100000
#define NP       100096   // padded to 1564*64 so GEMM A-loads need no guards
#define N_EDGES  1600000
#define N_GRAPHS 4096
#define DIM      128
#define HID      64
#define N_LAYERS 3
#define BN_EPS   1e-5f

#define SCAN_BLK 1024
#define N_SCAN_BLKS ((N_NODES + SCAN_BLK - 1) / SCAN_BLK)   // 98
#define GEMM_TILES (NP / 64)                                // 1564

// ---------------- device scratch (static, no allocation; BSS is zero-init) ----
__device__ float g_bufA[(size_t)NP * DIM];   // y ping (pad rows stay 0)
__device__ float g_bufB[(size_t)NP * DIM];   // y pong
__device__ float g_xf  [(size_t)NP * DIM];   // copy of input x (pad rows 0)
__device__ float g_agg [(size_t)NP * DIM];   // aggregated feats (pad rows 0)

// transposed+split weights: [layer*2 + (0=Wl,1=Wr)][N=128][K=128]
__device__ __nv_bfloat16 g_wthi[6 * DIM * DIM];
__device__ __nv_bfloat16 g_wtlo[6 * DIM * DIM];

__device__ int   g_deg[N_NODES];
__device__ float g_inv_deg[N_NODES];
__device__ int   g_row_start[N_NODES + 1];
__device__ int   g_cursor[N_NODES];
__device__ int   g_csr_src[N_EDGES];
__device__ int   g_scan_part[N_SCAN_BLKS];

__device__ float g_sum[DIM];
__device__ float g_sumsq[DIM];
__device__ float g_scale[DIM];
__device__ float g_shift[DIM];

__device__ float g_pooled[(size_t)N_GRAPHS * DIM];
__device__ int   g_cnt[N_GRAPHS];

__device__ __forceinline__ const float* sel_buf(int id) {
    return (id == 0) ? g_bufA : (id == 1) ? g_bufB : g_xf;
}
__device__ __forceinline__ float* sel_buf_w(int id) {
    return (id == 0) ? g_bufA : g_bufB;
}

// ---------------- helpers ----------------
__device__ __forceinline__ uint32_t smem_u32(const void* p) {
    uint32_t a;
    asm("{ .reg .u64 t; cvta.to.shared.u64 t, %1; cvt.u32.u64 %0, t; }" : "=r"(a) : "l"(p));
    return a;
}
#define SWZ128(o) ((o) ^ (((o) >> 3) & 0x70))

#define LDSM4(r0, r1, r2, r3, addr)                                          \
    asm volatile("ldmatrix.sync.aligned.m8n8.x4.shared.b16 {%0,%1,%2,%3}, [%4];" \
                 : "=r"(r0), "=r"(r1), "=r"(r2), "=r"(r3) : "r"(addr))

#define MMA16816(c0, c1, c2, c3, a0, a1, a2, a3, b0, b1)                     \
    asm volatile("mma.sync.aligned.m16n8k16.row.col.f32.bf16.bf16.f32 "      \
                 "{%0,%1,%2,%3}, {%4,%5,%6,%7}, {%8,%9}, {%0,%1,%2,%3};"     \
                 : "+f"(c0), "+f"(c1), "+f"(c2), "+f"(c3)                    \
                 : "r"(a0), "r"(a1), "r"(a2), "r"(a3), "r"(b0), "r"(b1))

__device__ __forceinline__ uint32_t pack_bf2(float a, float b) {
    __nv_bfloat162 h = __floats2bfloat162_rn(a, b);
    return *(uint32_t*)&h;
}
__device__ __forceinline__ void split_hi_lo(float v, float& hi, float& lo) {
    __nv_bfloat16 h = __float2bfloat16_rn(v);
    hi = __bfloat162float(h);
    lo = v - hi;
}
__device__ __forceinline__ void split2(float a, float b, uint32_t& H, uint32_t& L) {
    float ha, la, hb, lb;
    split_hi_lo(a, ha, la);
    split_hi_lo(b, hb, lb);
    H = pack_bf2(ha, hb);
    L = pack_bf2(la, lb);
}
__device__ __forceinline__ float4 affine_relu4(float4 v, float4 sc, float4 sh) {
    v.x = fmaxf(fmaf(v.x, sc.x, sh.x), 0.f);
    v.y = fmaxf(fmaf(v.y, sc.y, sh.y), 0.f);
    v.z = fmaxf(fmaf(v.z, sc.z, sh.z), 0.f);
    v.w = fmaxf(fmaf(v.w, sc.w, sh.w), 0.f);
    return v;
}

// ---------------- init ----------------
__global__ void init_kernel() {
    int i = blockIdx.x * blockDim.x + threadIdx.x;
    if (i < N_GRAPHS * DIM) g_pooled[i] = 0.f;
    if (i < N_NODES) { g_deg[i] = 0; g_cursor[i] = 0; }
    if (i < N_GRAPHS) g_cnt[i] = 0;
    if (i < DIM) { g_sum[i] = 0.f; g_sumsq[i] = 0.f; }
}

// ---------------- CSR build ----------------
__global__ void deg_kernel(const int* __restrict__ edge_dst) {
    int e = blockIdx.x * blockDim.x + threadIdx.x;
    if (e < N_EDGES) atomicAdd(&g_deg[edge_dst[e]], 1);
}
__global__ void cnt_kernel(const int* __restrict__ batch_ids) {
    int i = blockIdx.x * blockDim.x + threadIdx.x;
    if (i < N_NODES) atomicAdd(&g_cnt[batch_ids[i]], 1);
}
__global__ void scan1_kernel() {
    __shared__ int s[SCAN_BLK];
    int li = threadIdx.x;
    int gi = blockIdx.x * SCAN_BLK + li;
    int v = (gi < N_NODES) ? g_deg[gi] : 0;
    s[li] = v;
    __syncthreads();
    for (int off = 1; off < SCAN_BLK; off <<= 1) {
        int t = (li >= off) ? s[li - off] : 0;
        __syncthreads();
        s[li] += t;
        __syncthreads();
    }
    if (gi < N_NODES) g_row_start[gi] = s[li] - v;
    if (li == SCAN_BLK - 1) g_scan_part[blockIdx.x] = s[li];
}
__global__ void scan2_kernel() {
    if (threadIdx.x == 0 && blockIdx.x == 0) {
        int run = 0;
        for (int i = 0; i < N_SCAN_BLKS; i++) {
            int t = g_scan_part[i];
            g_scan_part[i] = run;
            run += t;
        }
    }
}
__global__ void scan3_kernel() {
    int i = blockIdx.x * blockDim.x + threadIdx.x;
    if (i < N_NODES) {
        g_row_start[i] += g_scan_part[i >> 10];
        g_inv_deg[i] = 1.0f / fmaxf((float)g_deg[i], 1.0f);
    }
    if (i == 0) g_row_start[N_NODES] = N_EDGES;
}
__global__ void csr_fill_kernel(const int* __restrict__ edge_src,
                                const int* __restrict__ edge_dst) {
    int e = blockIdx.x * blockDim.x + threadIdx.x;
    if (e < N_EDGES) {
        int d = edge_dst[e];
        int p = atomicAdd(&g_cursor[d], 1);
        g_csr_src[g_row_start[d] + p] = edge_src[e];
    }
}

// ---------------- weight transpose + hi/lo split ----------------
__global__ void wsplit_kernel(const float* __restrict__ Wl,
                              const float* __restrict__ Wr) {
    int b = blockIdx.x;                 // 0..5
    int l = b >> 1, which = b & 1;
    const float* src = (which ? Wr : Wl) + (size_t)l * DIM * DIM;
    for (int idx = threadIdx.x; idx < DIM * DIM; idx += blockDim.x) {
        int n = idx >> 7, k = idx & 127;
        float w = src[k * DIM + n];
        float hi, lo;
        split_hi_lo(w, hi, lo);
        g_wthi[(size_t)b * DIM * DIM + n * DIM + k] = __float2bfloat16_rn(hi);
        g_wtlo[(size_t)b * DIM * DIM + n * DIM + k] = __float2bfloat16_rn(lo);
    }
}

// ---------------- x -> g_xf copy (so padded GEMM tail never reads OOB) ----------
__global__ void copy_x_kernel(const float* __restrict__ x) {
    int q = blockIdx.x * blockDim.x + threadIdx.x;
    if (q < N_NODES * (DIM / 4))
        ((float4*)g_xf)[q] = ((const float4*)x)[q];
}

// ---------------- mean aggregation: one warp per node ----------------
// Gathers from src (pre-BN y of previous layer) applying affine+relu on the fly.
__global__ void agg_kernel(const float* __restrict__ xext, int src_id, int do_affine) {
    const float* __restrict__ xin = (src_id < 0) ? xext : sel_buf(src_id);
    int warp = (blockIdx.x * blockDim.x + threadIdx.x) >> 5;
    int lane = threadIdx.x & 31;
    if (warp >= N_NODES) return;
    int s = g_row_start[warp];
    int e = g_row_start[warp + 1];
    float4 sc = make_float4(1.f, 1.f, 1.f, 1.f);
    float4 sh = make_float4(0.f, 0.f, 0.f, 0.f);
    if (do_affine) {
        sc = *(const float4*)(g_scale + lane * 4);
        sh = *(const float4*)(g_shift + lane * 4);
    }
    float4 acc = make_float4(0.f, 0.f, 0.f, 0.f);
    if (do_affine) {
        for (int i = s; i < e; i++) {
            int src = g_csr_src[i];
            float4 v = *(const float4*)(xin + (size_t)src * DIM + lane * 4);
            v = affine_relu4(v, sc, sh);
            acc.x += v.x; acc.y += v.y; acc.z += v.z; acc.w += v.w;
        }
    } else {
        for (int i = s; i < e; i++) {
            int src = g_csr_src[i];
            float4 v = *(const float4*)(xin + (size_t)src * DIM + lane * 4);
            acc.x += v.x; acc.y += v.y; acc.z += v.z; acc.w += v.w;
        }
    }
    float inv = g_inv_deg[warp];
    acc.x *= inv; acc.y *= inv; acc.z *= inv; acc.w *= inv;
    *(float4*)(g_agg + (size_t)warp * DIM + lane * 4) = acc;
}

// ---------------- GEMM via mma.sync: y = agg@Wl + xnorm@Wr + b, fused BN sums --
// bf16x3: D += Ah*Bh + Al*Bh + Ah*Bl, fp32 accumulate.
// Block: 256 thr (8 warps = 2M x 4N), tile 64(M) x 128(N), K chunks of 64.
// SMEM: A-hi 8K + A-lo 8K + B-hi 16K + B-lo 16K = 48KB static.

// A tile: 64 rows x 64 fp32 from global (optional affine+relu), split hi/lo, SW128
__device__ __forceinline__ void copy_conv_a(char* dhi, char* dlo,
                                            const float* __restrict__ src,
                                            int affine, long grow0, int kc, int tid) {
    #pragma unroll
    for (int i = 0; i < 2; i++) {
        int idx = i * 256 + tid;            // 0..511 chunks of 8 floats
        int row = idx >> 3;
        int c8 = idx & 7;
        const float* p = src + (grow0 + row) * DIM + kc * 64 + c8 * 8;
        float4 v0 = *(const float4*)p;
        float4 v1 = *(const float4*)(p + 4);
        if (affine) {
            int col = kc * 64 + c8 * 8;
            float4 s0 = *(const float4*)(g_scale + col);
            float4 s1 = *(const float4*)(g_scale + col + 4);
            float4 t0 = *(const float4*)(g_shift + col);
            float4 t1 = *(const float4*)(g_shift + col + 4);
            v0 = affine_relu4(v0, s0, t0);
            v1 = affine_relu4(v1, s1, t1);
        }
        uint4 H, L;
        split2(v0.x, v0.y, H.x, L.x);
        split2(v0.z, v0.w, H.y, L.y);
        split2(v1.x, v1.y, H.z, L.z);
        split2(v1.z, v1.w, H.w, L.w);
        int off = SWZ128(row * 128 + c8 * 16);
        *(uint4*)(dhi + off) = H;
        *(uint4*)(dlo + off) = L;
    }
}
// B tile: 128 rows x 64 bf16
__device__ __forceinline__ void copy_tile_b(char* dst, const __nv_bfloat16* __restrict__ src,
                                            int kc, int tid) {
    #pragma unroll
    for (int i = 0; i < 4; i++) {
        int idx = i * 256 + tid;            // 0..1023
        int row = idx >> 3;
        int c = idx & 7;
        uint4 v = *(const uint4*)((const char*)src + (long)row * 256 + kc * 128 + c * 16);
        *(uint4*)(dst + SWZ128(row * 128 + c * 16)) = v;
    }
}

__device__ __forceinline__ uint32_t a_addr(uint32_t sbase, int rbase, int k16, int lane) {
    int row = rbase + ((lane >> 3) & 1) * 8 + (lane & 7);
    int kb  = k16 * 32 + (lane >> 4) * 16;
    return sbase + SWZ128(row * 128 + kb);
}
__device__ __forceinline__ uint32_t b_addr(uint32_t sbase, int nbase, int k16, int lane) {
    int row = nbase + ((lane >> 4) & 1) * 8 + (lane & 7);
    int kb  = k16 * 32 + ((lane >> 3) & 1) * 16;
    return sbase + SWZ128(row * 128 + kb);
}

__global__ void __launch_bounds__(256) gemm_mma_kernel(int layer,
                                                       const float* __restrict__ bias,
                                                       int a1_id, int a1_affine,
                                                       int out_id) {
    __shared__ char sAh[8192];
    __shared__ char sAl[8192];
    __shared__ char sBh[16384];
    __shared__ char sBl[16384];

    int tid = threadIdx.x;
    int wid = tid >> 5, lane = tid & 31;
    int wm = wid & 1;          // row group: wm*32
    int wn = wid >> 1;         // col group: wn*32
    long row0 = (long)blockIdx.x * 64;
    float* __restrict__ Y = sel_buf_w(out_id);

    uint32_t uAh = smem_u32(sAh), uAl = smem_u32(sAl);
    uint32_t uBh = smem_u32(sBh), uBl = smem_u32(sBl);

    float acc[2][4][4];
    #pragma unroll
    for (int m = 0; m < 2; m++)
        #pragma unroll
        for (int n = 0; n < 4; n++)
            #pragma unroll
            for (int k = 0; k < 4; k++) acc[m][n][k] = 0.f;

    #pragma unroll 1
    for (int s = 0; s < 2; s++) {
        const float* A = s ? sel_buf(a1_id) : g_agg;
        int aff = s ? a1_affine : 0;
        const __nv_bfloat16* Bh = g_wthi + (size_t)(layer * 2 + s) * DIM * DIM;
        const __nv_bfloat16* Bl = g_wtlo + (size_t)(layer * 2 + s) * DIM * DIM;

        #pragma unroll 1
        for (int kc = 0; kc < 2; kc++) {
            __syncthreads();
            copy_conv_a(sAh, sAl, A, aff, row0, kc, tid);
            copy_tile_b(sBh, Bh, kc, tid);
            copy_tile_b(sBl, Bl, kc, tid);
            __syncthreads();

            #pragma unroll
            for (int k16 = 0; k16 < 4; k16++) {
                uint32_t h0, h1, h2, h3, h4, h5, h6, h7;
                uint32_t l0, l1, l2, l3, l4, l5, l6, l7;
                uint32_t p0, p1, p2, p3, p4, p5, p6, p7;
                uint32_t q0, q1, q2, q3, q4, q5, q6, q7;
                LDSM4(h0, h1, h2, h3, a_addr(uAh, wm * 32 +  0, k16, lane));
                LDSM4(h4, h5, h6, h7, a_addr(uAh, wm * 32 + 16, k16, lane));
                LDSM4(l0, l1, l2, l3, a_addr(uAl, wm * 32 +  0, k16, lane));
                LDSM4(l4, l5, l6, l7, a_addr(uAl, wm * 32 + 16, k16, lane));
                LDSM4(p0, p1, p2, p3, b_addr(uBh, wn * 32 +  0, k16, lane));
                LDSM4(p4, p5, p6, p7, b_addr(uBh, wn * 32 + 16, k16, lane));
                LDSM4(q0, q1, q2, q3, b_addr(uBl, wn * 32 +  0, k16, lane));
                LDSM4(q4, q5, q6, q7, b_addr(uBl, wn * 32 + 16, k16, lane));
                // Ah*Bh
                MMA16816(acc[0][0][0], acc[0][0][1], acc[0][0][2], acc[0][0][3], h0, h1, h2, h3, p0, p1);
                MMA16816(acc[0][1][0], acc[0][1][1], acc[0][1][2], acc[0][1][3], h0, h1, h2, h3, p2, p3);
                MMA16816(acc[0][2][0], acc[0][2][1], acc[0][2][2], acc[0][2][3], h0, h1, h2, h3, p4, p5);
                MMA16816(acc[0][3][0], acc[0][3][1], acc[0][3][2], acc[0][3][3], h0, h1, h2, h3, p6, p7);
                MMA16816(acc[1][0][0], acc[1][0][1], acc[1][0][2], acc[1][0][3], h4, h5, h6, h7, p0, p1);
                MMA16816(acc[1][1][0], acc[1][1][1], acc[1][1][2], acc[1][1][3], h4, h5, h6, h7, p2, p3);
                MMA16816(acc[1][2][0], acc[1][2][1], acc[1][2][2], acc[1][2][3], h4, h5, h6, h7, p4, p5);
                MMA16816(acc[1][3][0], acc[1][3][1], acc[1][3][2], acc[1][3][3], h4, h5, h6, h7, p6, p7);
                // Al*Bh
                MMA16816(acc[0][0][0], acc[0][0][1], acc[0][0][2], acc[0][0][3], l0, l1, l2, l3, p0, p1);
                MMA16816(acc[0][1][0], acc[0][1][1], acc[0][1][2], acc[0][1][3], l0, l1, l2, l3, p2, p3);
                MMA16816(acc[0][2][0], acc[0][2][1], acc[0][2][2], acc[0][2][3], l0, l1, l2, l3, p4, p5);
                MMA16816(acc[0][3][0], acc[0][3][1], acc[0][3][2], acc[0][3][3], l0, l1, l2, l3, p6, p7);
                MMA16816(acc[1][0][0], acc[1][0][1], acc[1][0][2], acc[1][0][3], l4, l5, l6, l7, p0, p1);
                MMA16816(acc[1][1][0], acc[1][1][1], acc[1][1][2], acc[1][1][3], l4, l5, l6, l7, p2, p3);
                MMA16816(acc[1][2][0], acc[1][2][1], acc[1][2][2], acc[1][2][3], l4, l5, l6, l7, p4, p5);
                MMA16816(acc[1][3][0], acc[1][3][1], acc[1][3][2], acc[1][3][3], l4, l5, l6, l7, p6, p7);
                // Ah*Bl
                MMA16816(acc[0][0][0], acc[0][0][1], acc[0][0][2], acc[0][0][3], h0, h1, h2, h3, q0, q1);
                MMA16816(acc[0][1][0], acc[0][1][1], acc[0][1][2], acc[0][1][3], h0, h1, h2, h3, q2, q3);
                MMA16816(acc[0][2][0], acc[0][2][1], acc[0][2][2], acc[0][2][3], h0, h1, h2, h3, q4, q5);
                MMA16816(acc[0][3][0], acc[0][3][1], acc[0][3][2], acc[0][3][3], h0, h1, h2, h3, q6, q7);
                MMA16816(acc[1][0][0], acc[1][0][1], acc[1][0][2], acc[1][0][3], h4, h5, h6, h7, q0, q1);
                MMA16816(acc[1][1][0], acc[1][1][1], acc[1][1][2], acc[1][1][3], h4, h5, h6, h7, q2, q3);
                MMA16816(acc[1][2][0], acc[1][2][1], acc[1][2][2], acc[1][2][3], h4, h5, h6, h7, q4, q5);
                MMA16816(acc[1][3][0], acc[1][3][1], acc[1][3][2], acc[1][3][3], h4, h5, h6, h7, q6, q7);
            }
        }
    }

    // epilogue: store y = acc + bias, accumulate BN column sums
    int gr = lane >> 2, t2 = (lane & 3) * 2;
    float s1[4][2], s2[4][2];
    #pragma unroll
    for (int n = 0; n < 4; n++) {
        s1[n][0] = 0.f; s1[n][1] = 0.f;
        s2[n][0] = 0.f; s2[n][1] = 0.f;
    }
    #pragma unroll
    for (int m = 0; m < 2; m++) {
        long r = row0 + wm * 32 + m * 16 + gr;
        bool v0 = r < N_NODES, v1 = (r + 8) < N_NODES;
        #pragma unroll
        for (int n = 0; n < 4; n++) {
            int c = wn * 32 + n * 8 + t2;
            float2 bb = *(const float2*)(bias + c);
            float a0 = acc[m][n][0] + bb.x, a1 = acc[m][n][1] + bb.y;
            float a2 = acc[m][n][2] + bb.x, a3 = acc[m][n][3] + bb.y;
            if (v0) {
                *(float2*)(Y + r * DIM + c) = make_float2(a0, a1);
                s1[n][0] += a0; s2[n][0] += a0 * a0;
                s1[n][1] += a1; s2[n][1] += a1 * a1;
            }
            if (v1) {
                *(float2*)(Y + (r + 8) * DIM + c) = make_float2(a2, a3);
                s1[n][0] += a2; s2[n][0] += a2 * a2;
                s1[n][1] += a3; s2[n][1] += a3 * a3;
            }
        }
    }
    #pragma unroll
    for (int x = 4; x <= 16; x <<= 1) {
        #pragma unroll
        for (int n = 0; n < 4; n++) {
            s1[n][0] += __shfl_xor_sync(0xffffffffu, s1[n][0], x);
            s1[n][1] += __shfl_xor_sync(0xffffffffu, s1[n][1], x);
            s2[n][0] += __shfl_xor_sync(0xffffffffu, s2[n][0], x);
            s2[n][1] += __shfl_xor_sync(0xffffffffu, s2[n][1], x);
        }
    }
    if (lane < 4) {
        #pragma unroll
        for (int n = 0; n < 4; n++) {
            int c = wn * 32 + n * 8 + lane * 2;
            atomicAdd(&g_sum[c],     s1[n][0]);
            atomicAdd(&g_sum[c + 1], s1[n][1]);
            atomicAdd(&g_sumsq[c],     s2[n][0]);
            atomicAdd(&g_sumsq[c + 1], s2[n][1]);
        }
    }
}

// ---------------- BN finalize (+ self-reset for next layer) ----------------
__global__ void bnfinal_kernel(const float* __restrict__ gamma,
                               const float* __restrict__ beta) {
    int j = threadIdx.x;
    if (j < DIM) {
        const float invN = 1.0f / (float)N_NODES;
        float mu = g_sum[j] * invN;
        float var = g_sumsq[j] * invN - mu * mu;
        float rs = rsqrtf(var + BN_EPS);
        float sc = rs * gamma[j];
        g_scale[j] = sc;
        g_shift[j] = beta[j] - mu * sc;
        g_sum[j] = 0.f;
        g_sumsq[j] = 0.f;
    }
}

// ---------------- final pool: affine+relu on last y, atomic mean-pool ----------
__global__ void pool_kernel(const int* __restrict__ batch_ids, int y_id) {
    const float* __restrict__ y = sel_buf(y_id);
    int q = blockIdx.x * blockDim.x + threadIdx.x;
    if (q >= N_NODES * (DIM / 4)) return;
    int row = q >> 5;
    int j4 = (q & 31) * 4;
    float4 v = *(const float4*)(y + (size_t)row * DIM + j4);
    float4 sc = *(const float4*)(g_scale + j4);
    float4 sh = *(const float4*)(g_shift + j4);
    v = affine_relu4(v, sc, sh);
    float* p = g_pooled + (size_t)batch_ids[row] * DIM + j4;
    atomicAdd(p + 0, v.x);
    atomicAdd(p + 1, v.y);
    atomicAdd(p + 2, v.z);
    atomicAdd(p + 3, v.w);
}

// ---------------- MLP head: one block per graph ----------------
__global__ void head_kernel(const float* __restrict__ W1,
                            const float* __restrict__ b1,
                            const float* __restrict__ W2,
                            const float* __restrict__ b2,
                            float* __restrict__ out) {
    __shared__ float ph[DIM];
    __shared__ float h[HID];
    int g = blockIdx.x;
    int t = threadIdx.x;
    float invc = 1.0f / fmaxf((float)g_cnt[g], 1.0f);
    ph[t] = g_pooled[(size_t)g * DIM + t] * invc;
    __syncthreads();
    if (t < HID) {
        float acc = b1[t];
        #pragma unroll 4
        for (int k = 0; k < DIM; k++)
            acc += ph[k] * W1[k * HID + t];
        h[t] = fmaxf(acc, 0.f);
    }
    __syncthreads();
    if (t == 0) {
        float acc = b2[0];
        #pragma unroll
        for (int j = 0; j < HID; j++)
            acc += h[j] * W2[j];
        out[g] = acc;
    }
}

// ---------------- launch ----------------
extern "C" void kernel_launch(void* const* d_in, const int* in_sizes, int n_in,
                              void* d_out, int out_size) {
    const float* x     = (const float*)d_in[0];
    const float* Wl    = (const float*)d_in[1];
    const float* Wr    = (const float*)d_in[2];
    const float* b     = (const float*)d_in[3];
    const float* gamma = (const float*)d_in[4];
    const float* beta  = (const float*)d_in[5];
    const float* hW1   = (const float*)d_in[6];
    const float* hb1   = (const float*)d_in[7];
    const float* hW2   = (const float*)d_in[8];
    const float* hb2   = (const float*)d_in[9];
    const int* esrc    = (const int*)d_in[10];
    const int* edst    = (const int*)d_in[11];
    const int* bids    = (const int*)d_in[12];
    float* out = (float*)d_out;

    // --- graph structure + weight prep ---
    init_kernel<<<(N_GRAPHS * DIM + 255) / 256, 256>>>();
    deg_kernel<<<(N_EDGES + 255) / 256, 256>>>(edst);
    cnt_kernel<<<(N_NODES + 255) / 256, 256>>>(bids);
    scan1_kernel<<<N_SCAN_BLKS, SCAN_BLK>>>();
    scan2_kernel<<<1, 1>>>();
    scan3_kernel<<<(N_NODES + 255) / 256, 256>>>();
    csr_fill_kernel<<<(N_EDGES + 255) / 256, 256>>>(esrc, edst);
    wsplit_kernel<<<6, 256>>>(Wl, Wr);
    copy_x_kernel<<<(N_NODES * (DIM / 4) + 255) / 256, 256>>>(x);

    // --- 3 SAGE layers (y ping-pong: xf -> bufA -> bufB -> bufA) ---
    // layer 0: agg from x (no affine), self from g_xf (id 2), out bufA (0)
    agg_kernel<<<(N_NODES * 32 + 255) / 256, 256>>>(x, -1, 0);
    gemm_mma_kernel<<<GEMM_TILES, 256>>>(0, b, 2, 0, 0);
    bnfinal_kernel<<<1, 128>>>(gamma, beta);
    // layer 1: agg from bufA (affine L0), self from bufA (affine), out bufB (1)
    agg_kernel<<<(N_NODES * 32 + 255) / 256, 256>>>(nullptr, 0, 1);
    gemm_mma_kernel<<<GEMM_TILES, 256>>>(1, b + DIM, 0, 1, 1);
    bnfinal_kernel<<<1, 128>>>(gamma + DIM, beta + DIM);
    // layer 2: agg from bufB (affine L1), self from bufB (affine), out bufA (0)
    agg_kernel<<<(N_NODES * 32 + 255) / 256, 256>>>(nullptr, 1, 1);
    gemm_mma_kernel<<<GEMM_TILES, 256>>>(2, b + 2 * DIM, 1, 1, 0);
    bnfinal_kernel<<<1, 128>>>(gamma + 2 * DIM, beta + 2 * DIM);

    // --- final affine+relu+pool from bufA, then head ---
    pool_kernel<<<(N_NODES * (DIM / 4) + 255) / 256, 256>>>(bids, 0);
    head_kernel<<<N_GRAPHS, 128>>>(hW1, hb1, hW2, hb2, out);
}

// round 12
// speedup vs baseline: 1.0719x; 1.0719x over previous
#include <cuda_runtime.h>
#include <cuda_bf16.h>
#include <cuda_fp16.h>
#include <math.h>
#include <stdint.h>

#define N_NODES  100000
#define NP       100096   // padded to 1564*64 so GEMM A-loads need no guards
#define N_EDGES  1600000
#define N_GRAPHS 4096
#define DIM      128
#define HID      64
#define N_LAYERS 3
#define BN_EPS   1e-5f

#define SCAN_BLK 1024
#define N_SCAN_BLKS ((N_NODES + SCAN_BLK - 1) / SCAN_BLK)   // 98
#define GEMM_TILES (NP / 64)                                // 1564

// ---------------- device scratch (static, no allocation; BSS is zero-init) ----
__device__ float g_y  [(size_t)N_NODES * DIM];   // GEMM output (pre-BN)
__device__ float g_xf [(size_t)NP * DIM];        // activations fp32 (pad rows stay 0)
__device__ __half g_xh[(size_t)NP * DIM];        // fp16 mirror for agg gather
__device__ float g_agg[(size_t)NP * DIM];        // aggregated feats fp32 (pad rows 0)

// transposed+split weights: [layer*2 + (0=Wl,1=Wr)][N=128][K=128]
__device__ __nv_bfloat16 g_wthi[6 * DIM * DIM];
__device__ __nv_bfloat16 g_wtlo[6 * DIM * DIM];

__device__ int   g_deg[N_NODES];
__device__ float g_inv_deg[N_NODES];
__device__ int   g_row_start[N_NODES + 1];
__device__ int   g_cursor[N_NODES];
__device__ int   g_csr_src[N_EDGES];
__device__ int   g_scan_part[N_SCAN_BLKS];

__device__ float g_sum[DIM];
__device__ float g_sumsq[DIM];
__device__ float g_scale[DIM];
__device__ float g_shift[DIM];

__device__ float g_pooled[(size_t)N_GRAPHS * DIM];
__device__ int   g_cnt[N_GRAPHS];

// ---------------- helpers ----------------
__device__ __forceinline__ uint32_t smem_u32(const void* p) {
    uint32_t a;
    asm("{ .reg .u64 t; cvta.to.shared.u64 t, %1; cvt.u32.u64 %0, t; }" : "=r"(a) : "l"(p));
    return a;
}
#define SWZ128(o) ((o) ^ (((o) >> 3) & 0x70))

#define LDSM4(r0, r1, r2, r3, addr)                                          \
    asm volatile("ldmatrix.sync.aligned.m8n8.x4.shared.b16 {%0,%1,%2,%3}, [%4];" \
                 : "=r"(r0), "=r"(r1), "=r"(r2), "=r"(r3) : "r"(addr))

#define MMA16816(c0, c1, c2, c3, a0, a1, a2, a3, b0, b1)                     \
    asm volatile("mma.sync.aligned.m16n8k16.row.col.f32.bf16.bf16.f32 "      \
                 "{%0,%1,%2,%3}, {%4,%5,%6,%7}, {%8,%9}, {%0,%1,%2,%3};"     \
                 : "+f"(c0), "+f"(c1), "+f"(c2), "+f"(c3)                    \
                 : "r"(a0), "r"(a1), "r"(a2), "r"(a3), "r"(b0), "r"(b1))

__device__ __forceinline__ uint32_t pack_bf2(float a, float b) {
    __nv_bfloat162 h = __floats2bfloat162_rn(a, b);
    return *(uint32_t*)&h;
}
__device__ __forceinline__ void split_hi_lo(float v, float& hi, float& lo) {
    __nv_bfloat16 h = __float2bfloat16_rn(v);
    hi = __bfloat162float(h);
    lo = v - hi;
}
__device__ __forceinline__ void split2(float a, float b, uint32_t& H, uint32_t& L) {
    float ha, la, hb, lb;
    split_hi_lo(a, ha, la);
    split_hi_lo(b, hb, lb);
    H = pack_bf2(ha, hb);
    L = pack_bf2(la, lb);
}
__device__ __forceinline__ uint2 pack_h4(float4 v) {
    __half2 h0 = __floats2half2_rn(v.x, v.y);
    __half2 h1 = __floats2half2_rn(v.z, v.w);
    return make_uint2(*(uint32_t*)&h0, *(uint32_t*)&h1);
}

// ---------------- init ----------------
__global__ void init_kernel() {
    int i = blockIdx.x * blockDim.x + threadIdx.x;
    if (i < N_GRAPHS * DIM) g_pooled[i] = 0.f;
    if (i < N_NODES) { g_deg[i] = 0; g_cursor[i] = 0; }
    if (i < N_GRAPHS) g_cnt[i] = 0;
    if (i < DIM) { g_sum[i] = 0.f; g_sumsq[i] = 0.f; }
}

// ---------------- CSR build ----------------
__global__ void deg_kernel(const int* __restrict__ edge_dst) {
    int e = blockIdx.x * blockDim.x + threadIdx.x;
    if (e < N_EDGES) atomicAdd(&g_deg[edge_dst[e]], 1);
}
__global__ void cnt_kernel(const int* __restrict__ batch_ids) {
    int i = blockIdx.x * blockDim.x + threadIdx.x;
    if (i < N_NODES) atomicAdd(&g_cnt[batch_ids[i]], 1);
}
__global__ void scan1_kernel() {
    __shared__ int s[SCAN_BLK];
    int li = threadIdx.x;
    int gi = blockIdx.x * SCAN_BLK + li;
    int v = (gi < N_NODES) ? g_deg[gi] : 0;
    s[li] = v;
    __syncthreads();
    for (int off = 1; off < SCAN_BLK; off <<= 1) {
        int t = (li >= off) ? s[li - off] : 0;
        __syncthreads();
        s[li] += t;
        __syncthreads();
    }
    if (gi < N_NODES) g_row_start[gi] = s[li] - v;
    if (li == SCAN_BLK - 1) g_scan_part[blockIdx.x] = s[li];
}
__global__ void scan2_kernel() {
    if (threadIdx.x == 0 && blockIdx.x == 0) {
        int run = 0;
        for (int i = 0; i < N_SCAN_BLKS; i++) {
            int t = g_scan_part[i];
            g_scan_part[i] = run;
            run += t;
        }
    }
}
__global__ void scan3_kernel() {
    int i = blockIdx.x * blockDim.x + threadIdx.x;
    if (i < N_NODES) {
        g_row_start[i] += g_scan_part[i >> 10];
        g_inv_deg[i] = 1.0f / fmaxf((float)g_deg[i], 1.0f);
    }
    if (i == 0) g_row_start[N_NODES] = N_EDGES;
}
__global__ void csr_fill_kernel(const int* __restrict__ edge_src,
                                const int* __restrict__ edge_dst) {
    int e = blockIdx.x * blockDim.x + threadIdx.x;
    if (e < N_EDGES) {
        int d = edge_dst[e];
        int p = atomicAdd(&g_cursor[d], 1);
        g_csr_src[g_row_start[d] + p] = edge_src[e];
    }
}

// ---------------- weight transpose + hi/lo split ----------------
__global__ void wsplit_kernel(const float* __restrict__ Wl,
                              const float* __restrict__ Wr) {
    int b = blockIdx.x;                 // 0..5
    int l = b >> 1, which = b & 1;
    const float* src = (which ? Wr : Wl) + (size_t)l * DIM * DIM;
    for (int idx = threadIdx.x; idx < DIM * DIM; idx += blockDim.x) {
        int n = idx >> 7, k = idx & 127;
        float w = src[k * DIM + n];
        float hi, lo;
        split_hi_lo(w, hi, lo);
        g_wthi[(size_t)b * DIM * DIM + n * DIM + k] = __float2bfloat16_rn(hi);
        g_wtlo[(size_t)b * DIM * DIM + n * DIM + k] = __float2bfloat16_rn(lo);
    }
}

// ---------------- x -> g_xf fp32 + g_xh fp16 ----------
__global__ void copy_x_kernel(const float* __restrict__ x) {
    int q = blockIdx.x * blockDim.x + threadIdx.x;
    if (q < N_NODES * (DIM / 4)) {
        float4 v = ((const float4*)x)[q];
        ((float4*)g_xf)[q] = v;
        ((uint2*)g_xh)[q] = pack_h4(v);
    }
}

// ---------------- mean aggregation: one warp per node, fp16 gather ----------------
__global__ void agg_kernel() {
    int warp = (blockIdx.x * blockDim.x + threadIdx.x) >> 5;
    int lane = threadIdx.x & 31;
    if (warp >= N_NODES) return;
    int s = g_row_start[warp];
    int e = g_row_start[warp + 1];
    float4 acc = make_float4(0.f, 0.f, 0.f, 0.f);
    for (int i = s; i < e; i++) {
        int src = g_csr_src[i];
        uint2 u = *(const uint2*)(g_xh + (size_t)src * DIM + lane * 4);
        float2 fa = __half22float2(*(__half2*)&u.x);
        float2 fb = __half22float2(*(__half2*)&u.y);
        acc.x += fa.x; acc.y += fa.y; acc.z += fb.x; acc.w += fb.y;
    }
    float inv = g_inv_deg[warp];
    acc.x *= inv; acc.y *= inv; acc.z *= inv; acc.w *= inv;
    *(float4*)(g_agg + (size_t)warp * DIM + lane * 4) = acc;
}

// ---------------- GEMM via mma.sync: y = agg@Wl + x@Wr + b, fused BN sums ------
// bf16x3: D += Ah*Bh + Al*Bh + Ah*Bl, fp32 accumulate.
// Block: 256 thr (8 warps = 2M x 4N), tile 64(M) x 128(N), K chunks of 64.
// SMEM: A-hi 8K + A-lo 8K + B-hi 16K + B-lo 16K = 48KB static.

__device__ __forceinline__ void copy_conv_a(char* dhi, char* dlo,
                                            const float* __restrict__ src,
                                            long grow0, int kc, int tid) {
    #pragma unroll
    for (int i = 0; i < 2; i++) {
        int idx = i * 256 + tid;            // 0..511 chunks of 8 floats
        int row = idx >> 3;
        int c8 = idx & 7;
        const float* p = src + (grow0 + row) * DIM + kc * 64 + c8 * 8;
        float4 v0 = *(const float4*)p;
        float4 v1 = *(const float4*)(p + 4);
        uint4 H, L;
        split2(v0.x, v0.y, H.x, L.x);
        split2(v0.z, v0.w, H.y, L.y);
        split2(v1.x, v1.y, H.z, L.z);
        split2(v1.z, v1.w, H.w, L.w);
        int off = SWZ128(row * 128 + c8 * 16);
        *(uint4*)(dhi + off) = H;
        *(uint4*)(dlo + off) = L;
    }
}
__device__ __forceinline__ void copy_tile_b(char* dst, const __nv_bfloat16* __restrict__ src,
                                            int kc, int tid) {
    #pragma unroll
    for (int i = 0; i < 4; i++) {
        int idx = i * 256 + tid;            // 0..1023
        int row = idx >> 3;
        int c = idx & 7;
        uint4 v = *(const uint4*)((const char*)src + (long)row * 256 + kc * 128 + c * 16);
        *(uint4*)(dst + SWZ128(row * 128 + c * 16)) = v;
    }
}

__device__ __forceinline__ uint32_t a_addr(uint32_t sbase, int rbase, int k16, int lane) {
    int row = rbase + ((lane >> 3) & 1) * 8 + (lane & 7);
    int kb  = k16 * 32 + (lane >> 4) * 16;
    return sbase + SWZ128(row * 128 + kb);
}
__device__ __forceinline__ uint32_t b_addr(uint32_t sbase, int nbase, int k16, int lane) {
    int row = nbase + ((lane >> 4) & 1) * 8 + (lane & 7);
    int kb  = k16 * 32 + ((lane >> 3) & 1) * 16;
    return sbase + SWZ128(row * 128 + kb);
}

__global__ void __launch_bounds__(256) gemm_mma_kernel(int layer,
                                                       const float* __restrict__ bias) {
    __shared__ char sAh[8192];
    __shared__ char sAl[8192];
    __shared__ char sBh[16384];
    __shared__ char sBl[16384];

    int tid = threadIdx.x;
    int wid = tid >> 5, lane = tid & 31;
    int wm = wid & 1;          // row group: wm*32
    int wn = wid >> 1;         // col group: wn*32
    long row0 = (long)blockIdx.x * 64;

    uint32_t uAh = smem_u32(sAh), uAl = smem_u32(sAl);
    uint32_t uBh = smem_u32(sBh), uBl = smem_u32(sBl);

    float acc[2][4][4];
    #pragma unroll
    for (int m = 0; m < 2; m++)
        #pragma unroll
        for (int n = 0; n < 4; n++)
            #pragma unroll
            for (int k = 0; k < 4; k++) acc[m][n][k] = 0.f;

    #pragma unroll 1
    for (int s = 0; s < 2; s++) {
        const float* A = s ? g_xf : g_agg;
        const __nv_bfloat16* Bh = g_wthi + (size_t)(layer * 2 + s) * DIM * DIM;
        const __nv_bfloat16* Bl = g_wtlo + (size_t)(layer * 2 + s) * DIM * DIM;

        #pragma unroll 1
        for (int kc = 0; kc < 2; kc++) {
            __syncthreads();
            copy_conv_a(sAh, sAl, A, row0, kc, tid);
            copy_tile_b(sBh, Bh, kc, tid);
            copy_tile_b(sBl, Bl, kc, tid);
            __syncthreads();

            #pragma unroll
            for (int k16 = 0; k16 < 4; k16++) {
                uint32_t h0, h1, h2, h3, h4, h5, h6, h7;
                uint32_t l0, l1, l2, l3, l4, l5, l6, l7;
                uint32_t p0, p1, p2, p3, p4, p5, p6, p7;
                uint32_t q0, q1, q2, q3, q4, q5, q6, q7;
                LDSM4(h0, h1, h2, h3, a_addr(uAh, wm * 32 +  0, k16, lane));
                LDSM4(h4, h5, h6, h7, a_addr(uAh, wm * 32 + 16, k16, lane));
                LDSM4(l0, l1, l2, l3, a_addr(uAl, wm * 32 +  0, k16, lane));
                LDSM4(l4, l5, l6, l7, a_addr(uAl, wm * 32 + 16, k16, lane));
                LDSM4(p0, p1, p2, p3, b_addr(uBh, wn * 32 +  0, k16, lane));
                LDSM4(p4, p5, p6, p7, b_addr(uBh, wn * 32 + 16, k16, lane));
                LDSM4(q0, q1, q2, q3, b_addr(uBl, wn * 32 +  0, k16, lane));
                LDSM4(q4, q5, q6, q7, b_addr(uBl, wn * 32 + 16, k16, lane));
                // Ah*Bh
                MMA16816(acc[0][0][0], acc[0][0][1], acc[0][0][2], acc[0][0][3], h0, h1, h2, h3, p0, p1);
                MMA16816(acc[0][1][0], acc[0][1][1], acc[0][1][2], acc[0][1][3], h0, h1, h2, h3, p2, p3);
                MMA16816(acc[0][2][0], acc[0][2][1], acc[0][2][2], acc[0][2][3], h0, h1, h2, h3, p4, p5);
                MMA16816(acc[0][3][0], acc[0][3][1], acc[0][3][2], acc[0][3][3], h0, h1, h2, h3, p6, p7);
                MMA16816(acc[1][0][0], acc[1][0][1], acc[1][0][2], acc[1][0][3], h4, h5, h6, h7, p0, p1);
                MMA16816(acc[1][1][0], acc[1][1][1], acc[1][1][2], acc[1][1][3], h4, h5, h6, h7, p2, p3);
                MMA16816(acc[1][2][0], acc[1][2][1], acc[1][2][2], acc[1][2][3], h4, h5, h6, h7, p4, p5);
                MMA16816(acc[1][3][0], acc[1][3][1], acc[1][3][2], acc[1][3][3], h4, h5, h6, h7, p6, p7);
                // Al*Bh
                MMA16816(acc[0][0][0], acc[0][0][1], acc[0][0][2], acc[0][0][3], l0, l1, l2, l3, p0, p1);
                MMA16816(acc[0][1][0], acc[0][1][1], acc[0][1][2], acc[0][1][3], l0, l1, l2, l3, p2, p3);
                MMA16816(acc[0][2][0], acc[0][2][1], acc[0][2][2], acc[0][2][3], l0, l1, l2, l3, p4, p5);
                MMA16816(acc[0][3][0], acc[0][3][1], acc[0][3][2], acc[0][3][3], l0, l1, l2, l3, p6, p7);
                MMA16816(acc[1][0][0], acc[1][0][1], acc[1][0][2], acc[1][0][3], l4, l5, l6, l7, p0, p1);
                MMA16816(acc[1][1][0], acc[1][1][1], acc[1][1][2], acc[1][1][3], l4, l5, l6, l7, p2, p3);
                MMA16816(acc[1][2][0], acc[1][2][1], acc[1][2][2], acc[1][2][3], l4, l5, l6, l7, p4, p5);
                MMA16816(acc[1][3][0], acc[1][3][1], acc[1][3][2], acc[1][3][3], l4, l5, l6, l7, p6, p7);
                // Ah*Bl
                MMA16816(acc[0][0][0], acc[0][0][1], acc[0][0][2], acc[0][0][3], h0, h1, h2, h3, q0, q1);
                MMA16816(acc[0][1][0], acc[0][1][1], acc[0][1][2], acc[0][1][3], h0, h1, h2, h3, q2, q3);
                MMA16816(acc[0][2][0], acc[0][2][1], acc[0][2][2], acc[0][2][3], h0, h1, h2, h3, q4, q5);
                MMA16816(acc[0][3][0], acc[0][3][1], acc[0][3][2], acc[0][3][3], h0, h1, h2, h3, q6, q7);
                MMA16816(acc[1][0][0], acc[1][0][1], acc[1][0][2], acc[1][0][3], h4, h5, h6, h7, q0, q1);
                MMA16816(acc[1][1][0], acc[1][1][1], acc[1][1][2], acc[1][1][3], h4, h5, h6, h7, q2, q3);
                MMA16816(acc[1][2][0], acc[1][2][1], acc[1][2][2], acc[1][2][3], h4, h5, h6, h7, q4, q5);
                MMA16816(acc[1][3][0], acc[1][3][1], acc[1][3][2], acc[1][3][3], h4, h5, h6, h7, q6, q7);
            }
        }
    }

    // epilogue: store y = acc + bias, accumulate BN column sums
    int gr = lane >> 2, t2 = (lane & 3) * 2;
    float s1[4][2], s2[4][2];
    #pragma unroll
    for (int n = 0; n < 4; n++) {
        s1[n][0] = 0.f; s1[n][1] = 0.f;
        s2[n][0] = 0.f; s2[n][1] = 0.f;
    }
    #pragma unroll
    for (int m = 0; m < 2; m++) {
        long r = row0 + wm * 32 + m * 16 + gr;
        bool v0 = r < N_NODES, v1 = (r + 8) < N_NODES;
        #pragma unroll
        for (int n = 0; n < 4; n++) {
            int c = wn * 32 + n * 8 + t2;
            float2 bb = *(const float2*)(bias + c);
            float a0 = acc[m][n][0] + bb.x, a1 = acc[m][n][1] + bb.y;
            float a2 = acc[m][n][2] + bb.x, a3 = acc[m][n][3] + bb.y;
            if (v0) {
                *(float2*)(g_y + r * DIM + c) = make_float2(a0, a1);
                s1[n][0] += a0; s2[n][0] += a0 * a0;
                s1[n][1] += a1; s2[n][1] += a1 * a1;
            }
            if (v1) {
                *(float2*)(g_y + (r + 8) * DIM + c) = make_float2(a2, a3);
                s1[n][0] += a2; s2[n][0] += a2 * a2;
                s1[n][1] += a3; s2[n][1] += a3 * a3;
            }
        }
    }
    #pragma unroll
    for (int x = 4; x <= 16; x <<= 1) {
        #pragma unroll
        for (int n = 0; n < 4; n++) {
            s1[n][0] += __shfl_xor_sync(0xffffffffu, s1[n][0], x);
            s1[n][1] += __shfl_xor_sync(0xffffffffu, s1[n][1], x);
            s2[n][0] += __shfl_xor_sync(0xffffffffu, s2[n][0], x);
            s2[n][1] += __shfl_xor_sync(0xffffffffu, s2[n][1], x);
        }
    }
    if (lane < 4) {
        #pragma unroll
        for (int n = 0; n < 4; n++) {
            int c = wn * 32 + n * 8 + lane * 2;
            atomicAdd(&g_sum[c],     s1[n][0]);
            atomicAdd(&g_sum[c + 1], s1[n][1]);
            atomicAdd(&g_sumsq[c],     s2[n][0]);
            atomicAdd(&g_sumsq[c + 1], s2[n][1]);
        }
    }
}

// ---------------- BN finalize (+ self-reset for next layer) ----------------
__global__ void bnfinal_kernel(const float* __restrict__ gamma,
                               const float* __restrict__ beta) {
    int j = threadIdx.x;
    if (j < DIM) {
        const float invN = 1.0f / (float)N_NODES;
        float mu = g_sum[j] * invN;
        float var = g_sumsq[j] * invN - mu * mu;
        float rs = rsqrtf(var + BN_EPS);
        float sc = rs * gamma[j];
        g_scale[j] = sc;
        g_shift[j] = beta[j] - mu * sc;
        g_sum[j] = 0.f;
        g_sumsq[j] = 0.f;
    }
}

// ---------------- normalize + ReLU -> g_xf fp32 + g_xh fp16 (+ pool last) ------
__global__ void norm_kernel(const int* __restrict__ batch_ids, int write_x, int do_pool) {
    int q = blockIdx.x * blockDim.x + threadIdx.x;
    if (q >= N_NODES * (DIM / 4)) return;
    int row = q >> 5;
    int j4 = (q & 31) * 4;
    float4 v = *(const float4*)(g_y + (size_t)row * DIM + j4);
    float4 sc = *(const float4*)(g_scale + j4);
    float4 sh = *(const float4*)(g_shift + j4);
    v.x = fmaxf(fmaf(v.x, sc.x, sh.x), 0.f);
    v.y = fmaxf(fmaf(v.y, sc.y, sh.y), 0.f);
    v.z = fmaxf(fmaf(v.z, sc.z, sh.z), 0.f);
    v.w = fmaxf(fmaf(v.w, sc.w, sh.w), 0.f);
    if (write_x) {
        *(float4*)(g_xf + (size_t)row * DIM + j4) = v;
        *(uint2*)(g_xh + (size_t)row * DIM + j4) = pack_h4(v);
    }
    if (do_pool) {
        float* p = g_pooled + (size_t)batch_ids[row] * DIM + j4;
        atomicAdd(p + 0, v.x);
        atomicAdd(p + 1, v.y);
        atomicAdd(p + 2, v.z);
        atomicAdd(p + 3, v.w);
    }
}

// ---------------- MLP head: one block per graph ----------------
__global__ void head_kernel(const float* __restrict__ W1,
                            const float* __restrict__ b1,
                            const float* __restrict__ W2,
                            const float* __restrict__ b2,
                            float* __restrict__ out) {
    __shared__ float ph[DIM];
    __shared__ float h[HID];
    int g = blockIdx.x;
    int t = threadIdx.x;
    float invc = 1.0f / fmaxf((float)g_cnt[g], 1.0f);
    ph[t] = g_pooled[(size_t)g * DIM + t] * invc;
    __syncthreads();
    if (t < HID) {
        float acc = b1[t];
        #pragma unroll 4
        for (int k = 0; k < DIM; k++)
            acc += ph[k] * W1[k * HID + t];
        h[t] = fmaxf(acc, 0.f);
    }
    __syncthreads();
    if (t == 0) {
        float acc = b2[0];
        #pragma unroll
        for (int j = 0; j < HID; j++)
            acc += h[j] * W2[j];
        out[g] = acc;
    }
}

// ---------------- launch ----------------
extern "C" void kernel_launch(void* const* d_in, const int* in_sizes, int n_in,
                              void* d_out, int out_size) {
    const float* x     = (const float*)d_in[0];
    const float* Wl    = (const float*)d_in[1];
    const float* Wr    = (const float*)d_in[2];
    const float* b     = (const float*)d_in[3];
    const float* gamma = (const float*)d_in[4];
    const float* beta  = (const float*)d_in[5];
    const float* hW1   = (const float*)d_in[6];
    const float* hb1   = (const float*)d_in[7];
    const float* hW2   = (const float*)d_in[8];
    const float* hb2   = (const float*)d_in[9];
    const int* esrc    = (const int*)d_in[10];
    const int* edst    = (const int*)d_in[11];
    const int* bids    = (const int*)d_in[12];
    float* out = (float*)d_out;

    // --- graph structure + weight prep ---
    init_kernel<<<(N_GRAPHS * DIM + 255) / 256, 256>>>();
    deg_kernel<<<(N_EDGES + 255) / 256, 256>>>(edst);
    cnt_kernel<<<(N_NODES + 255) / 256, 256>>>(bids);
    scan1_kernel<<<N_SCAN_BLKS, SCAN_BLK>>>();
    scan2_kernel<<<1, 1>>>();
    scan3_kernel<<<(N_NODES + 255) / 256, 256>>>();
    csr_fill_kernel<<<(N_EDGES + 255) / 256, 256>>>(esrc, edst);
    wsplit_kernel<<<6, 256>>>(Wl, Wr);
    copy_x_kernel<<<(N_NODES * (DIM / 4) + 255) / 256, 256>>>(x);

    // --- 3 SAGE layers ---
    for (int l = 0; l < N_LAYERS; l++) {
        agg_kernel<<<(N_NODES * 32 + 255) / 256, 256>>>();
        gemm_mma_kernel<<<GEMM_TILES, 256>>>(l, b + (size_t)l * DIM);
        bnfinal_kernel<<<1, 128>>>(gamma + (size_t)l * DIM, beta + (size_t)l * DIM);
        norm_kernel<<<(N_NODES * (DIM / 4) + 255) / 256, 256>>>(
            bids, l < N_LAYERS - 1, l == N_LAYERS - 1);
    }

    // --- head ---
    head_kernel<<<N_GRAPHS, 128>>>(hW1, hb1, hW2, hb2, out);
}

// round 13
// speedup vs baseline: 1.1381x; 1.0618x over previous
#include <cuda_runtime.h>
#include <cuda_bf16.h>
#include <cuda_fp16.h>
#include <math.h>
#include <stdint.h>

#define N_NODES  100000
#define NP       100096   // padded to 1564*64 so GEMM A-loads need no guards
#define N_EDGES  1600000
#define N_GRAPHS 4096
#define DIM      128
#define HID      64
#define N_LAYERS 3
#define BN_EPS   1e-5f

#define SCAN_BLK 1024
#define N_SCAN_BLKS ((N_NODES + SCAN_BLK - 1) / SCAN_BLK)   // 98
#define GEMM_TILES (NP / 64)                                // 1564

// ---------------- device scratch (static, no allocation; BSS is zero-init) ----
__device__ float g_y  [(size_t)N_NODES * DIM];      // GEMM output (pre-BN)
__device__ __nv_bfloat16 g_xhi[(size_t)NP * DIM];   // normalized acts hi (pad rows 0)
__device__ __nv_bfloat16 g_xlo[(size_t)NP * DIM];   // normalized acts lo
__device__ __half        g_xh [(size_t)NP * DIM];   // fp16 mirror for agg gather
__device__ __nv_bfloat16 g_ahi[(size_t)NP * DIM];   // aggregated hi
__device__ __nv_bfloat16 g_alo[(size_t)NP * DIM];   // aggregated lo

// transposed+split weights: [layer*2 + (0=Wl,1=Wr)][N=128][K=128]
__device__ __nv_bfloat16 g_wthi[6 * DIM * DIM];
__device__ __nv_bfloat16 g_wtlo[6 * DIM * DIM];

__device__ int   g_deg[N_NODES];
__device__ float g_inv_deg[N_NODES];
__device__ int   g_row_start[N_NODES + 1];
__device__ int   g_cursor[N_NODES];
__device__ int   g_csr_src[N_EDGES];
__device__ int   g_scan_part[N_SCAN_BLKS];

__device__ float g_sum[DIM];
__device__ float g_sumsq[DIM];
__device__ float g_scale[DIM];
__device__ float g_shift[DIM];

__device__ float g_pooled[(size_t)N_GRAPHS * DIM];
__device__ int   g_cnt[N_GRAPHS];

// ---------------- helpers ----------------
__device__ __forceinline__ uint32_t smem_u32(const void* p) {
    uint32_t a;
    asm("{ .reg .u64 t; cvta.to.shared.u64 t, %1; cvt.u32.u64 %0, t; }" : "=r"(a) : "l"(p));
    return a;
}
#define SWZ128(o) ((o) ^ (((o) >> 3) & 0x70))

#define LDSM4(r0, r1, r2, r3, addr)                                          \
    asm volatile("ldmatrix.sync.aligned.m8n8.x4.shared.b16 {%0,%1,%2,%3}, [%4];" \
                 : "=r"(r0), "=r"(r1), "=r"(r2), "=r"(r3) : "r"(addr))

#define MMA16816(c0, c1, c2, c3, a0, a1, a2, a3, b0, b1)                     \
    asm volatile("mma.sync.aligned.m16n8k16.row.col.f32.bf16.bf16.f32 "      \
                 "{%0,%1,%2,%3}, {%4,%5,%6,%7}, {%8,%9}, {%0,%1,%2,%3};"     \
                 : "+f"(c0), "+f"(c1), "+f"(c2), "+f"(c3)                    \
                 : "r"(a0), "r"(a1), "r"(a2), "r"(a3), "r"(b0), "r"(b1))

__device__ __forceinline__ uint32_t pack_bf2(float a, float b) {
    __nv_bfloat162 h = __floats2bfloat162_rn(a, b);
    return *(uint32_t*)&h;
}
__device__ __forceinline__ void split_hi_lo(float v, float& hi, float& lo) {
    __nv_bfloat16 h = __float2bfloat16_rn(v);
    hi = __bfloat162float(h);
    lo = v - hi;
}
__device__ __forceinline__ void split2(float a, float b, uint32_t& H, uint32_t& L) {
    float ha, la, hb, lb;
    split_hi_lo(a, ha, la);
    split_hi_lo(b, hb, lb);
    H = pack_bf2(ha, hb);
    L = pack_bf2(la, lb);
}
__device__ __forceinline__ void split4(float4 v, uint2& H, uint2& L) {
    split2(v.x, v.y, H.x, L.x);
    split2(v.z, v.w, H.y, L.y);
}
__device__ __forceinline__ uint2 pack_h4(float4 v) {
    __half2 h0 = __floats2half2_rn(v.x, v.y);
    __half2 h1 = __floats2half2_rn(v.z, v.w);
    return make_uint2(*(uint32_t*)&h0, *(uint32_t*)&h1);
}

// ---------------- init ----------------
__global__ void init_kernel() {
    int i = blockIdx.x * blockDim.x + threadIdx.x;
    if (i < N_GRAPHS * DIM) g_pooled[i] = 0.f;
    if (i < N_NODES) { g_deg[i] = 0; g_cursor[i] = 0; }
    if (i < N_GRAPHS) g_cnt[i] = 0;
    if (i < DIM) { g_sum[i] = 0.f; g_sumsq[i] = 0.f; }
}

// ---------------- CSR build ----------------
__global__ void deg_kernel(const int* __restrict__ edge_dst) {
    int e = blockIdx.x * blockDim.x + threadIdx.x;
    if (e < N_EDGES) atomicAdd(&g_deg[edge_dst[e]], 1);
}
__global__ void cnt_kernel(const int* __restrict__ batch_ids) {
    int i = blockIdx.x * blockDim.x + threadIdx.x;
    if (i < N_NODES) atomicAdd(&g_cnt[batch_ids[i]], 1);
}
__global__ void scan1_kernel() {
    __shared__ int s[SCAN_BLK];
    int li = threadIdx.x;
    int gi = blockIdx.x * SCAN_BLK + li;
    int v = (gi < N_NODES) ? g_deg[gi] : 0;
    s[li] = v;
    __syncthreads();
    for (int off = 1; off < SCAN_BLK; off <<= 1) {
        int t = (li >= off) ? s[li - off] : 0;
        __syncthreads();
        s[li] += t;
        __syncthreads();
    }
    if (gi < N_NODES) g_row_start[gi] = s[li] - v;
    if (li == SCAN_BLK - 1) g_scan_part[blockIdx.x] = s[li];
}
__global__ void scan2_kernel() {
    if (threadIdx.x == 0 && blockIdx.x == 0) {
        int run = 0;
        for (int i = 0; i < N_SCAN_BLKS; i++) {
            int t = g_scan_part[i];
            g_scan_part[i] = run;
            run += t;
        }
    }
}
__global__ void scan3_kernel() {
    int i = blockIdx.x * blockDim.x + threadIdx.x;
    if (i < N_NODES) {
        g_row_start[i] += g_scan_part[i >> 10];
        g_inv_deg[i] = 1.0f / fmaxf((float)g_deg[i], 1.0f);
    }
    if (i == 0) g_row_start[N_NODES] = N_EDGES;
}
__global__ void csr_fill_kernel(const int* __restrict__ edge_src,
                                const int* __restrict__ edge_dst) {
    int e = blockIdx.x * blockDim.x + threadIdx.x;
    if (e < N_EDGES) {
        int d = edge_dst[e];
        int p = atomicAdd(&g_cursor[d], 1);
        g_csr_src[g_row_start[d] + p] = edge_src[e];
    }
}

// ---------------- weight transpose + hi/lo split ----------------
__global__ void wsplit_kernel(const float* __restrict__ Wl,
                              const float* __restrict__ Wr) {
    int b = blockIdx.x;                 // 0..5
    int l = b >> 1, which = b & 1;
    const float* src = (which ? Wr : Wl) + (size_t)l * DIM * DIM;
    for (int idx = threadIdx.x; idx < DIM * DIM; idx += blockDim.x) {
        int n = idx >> 7, k = idx & 127;
        float w = src[k * DIM + n];
        float hi, lo;
        split_hi_lo(w, hi, lo);
        g_wthi[(size_t)b * DIM * DIM + n * DIM + k] = __float2bfloat16_rn(hi);
        g_wtlo[(size_t)b * DIM * DIM + n * DIM + k] = __float2bfloat16_rn(lo);
    }
}

// ---------------- x -> xhi/xlo bf16 + xh fp16 ----------
__global__ void copy_x_kernel(const float* __restrict__ x) {
    int q = blockIdx.x * blockDim.x + threadIdx.x;
    if (q < N_NODES * (DIM / 4)) {
        float4 v = ((const float4*)x)[q];
        uint2 H, L;
        split4(v, H, L);
        ((uint2*)g_xhi)[q] = H;
        ((uint2*)g_xlo)[q] = L;
        ((uint2*)g_xh)[q] = pack_h4(v);
    }
}

// ---------------- mean aggregation: one warp per node, fp16 gather -> hi/lo bf16 ----
__global__ void agg_kernel() {
    int warp = (blockIdx.x * blockDim.x + threadIdx.x) >> 5;
    int lane = threadIdx.x & 31;
    if (warp >= N_NODES) return;
    int s = g_row_start[warp];
    int e = g_row_start[warp + 1];
    float4 acc = make_float4(0.f, 0.f, 0.f, 0.f);
    for (int i = s; i < e; i++) {
        int src = g_csr_src[i];
        uint2 u = *(const uint2*)(g_xh + (size_t)src * DIM + lane * 4);
        float2 fa = __half22float2(*(__half2*)&u.x);
        float2 fb = __half22float2(*(__half2*)&u.y);
        acc.x += fa.x; acc.y += fa.y; acc.z += fb.x; acc.w += fb.y;
    }
    float inv = g_inv_deg[warp];
    acc.x *= inv; acc.y *= inv; acc.z *= inv; acc.w *= inv;
    uint2 H, L;
    split4(acc, H, L);
    *(uint2*)(g_ahi + (size_t)warp * DIM + lane * 4) = H;
    *(uint2*)(g_alo + (size_t)warp * DIM + lane * 4) = L;
}

// ---------------- GEMM via mma.sync: y = agg@Wl + x@Wr + b, fused BN sums ------
// bf16x3: D += Ah*Bh + Al*Bh + Ah*Bl, fp32 accumulate.
// Block: 256 thr (8 warps = 2M x 4N), tile 64(M) x 128(N), K chunks of 64.
// SMEM: A-hi 8K + A-lo 8K + B-hi 16K + B-lo 16K = 48KB static.
// A operands are pre-split bf16 -> copy phase is pure uint4 moves.

// A tile: 64 rows x 64 bf16 (128B/row) from global (row stride 256B), SW128-swizzled
__device__ __forceinline__ void copy_tile_a(char* dst, const __nv_bfloat16* __restrict__ src,
                                            long grow0, int kc, int tid) {
    #pragma unroll
    for (int i = 0; i < 2; i++) {
        int idx = i * 256 + tid;            // 0..511
        int row = idx >> 3;
        int c = idx & 7;
        uint4 v = *(const uint4*)((const char*)src + (grow0 + row) * 256 + kc * 128 + c * 16);
        *(uint4*)(dst + SWZ128(row * 128 + c * 16)) = v;
    }
}
// B tile: 128 rows x 64 bf16
__device__ __forceinline__ void copy_tile_b(char* dst, const __nv_bfloat16* __restrict__ src,
                                            int kc, int tid) {
    #pragma unroll
    for (int i = 0; i < 4; i++) {
        int idx = i * 256 + tid;            // 0..1023
        int row = idx >> 3;
        int c = idx & 7;
        uint4 v = *(const uint4*)((const char*)src + (long)row * 256 + kc * 128 + c * 16);
        *(uint4*)(dst + SWZ128(row * 128 + c * 16)) = v;
    }
}

__device__ __forceinline__ uint32_t a_addr(uint32_t sbase, int rbase, int k16, int lane) {
    int row = rbase + ((lane >> 3) & 1) * 8 + (lane & 7);
    int kb  = k16 * 32 + (lane >> 4) * 16;
    return sbase + SWZ128(row * 128 + kb);
}
__device__ __forceinline__ uint32_t b_addr(uint32_t sbase, int nbase, int k16, int lane) {
    int row = nbase + ((lane >> 4) & 1) * 8 + (lane & 7);
    int kb  = k16 * 32 + ((lane >> 3) & 1) * 16;
    return sbase + SWZ128(row * 128 + kb);
}

__global__ void __launch_bounds__(256) gemm_mma_kernel(int layer,
                                                       const float* __restrict__ bias) {
    __shared__ char sAh[8192];
    __shared__ char sAl[8192];
    __shared__ char sBh[16384];
    __shared__ char sBl[16384];

    int tid = threadIdx.x;
    int wid = tid >> 5, lane = tid & 31;
    int wm = wid & 1;          // row group: wm*32
    int wn = wid >> 1;         // col group: wn*32
    long row0 = (long)blockIdx.x * 64;

    uint32_t uAh = smem_u32(sAh), uAl = smem_u32(sAl);
    uint32_t uBh = smem_u32(sBh), uBl = smem_u32(sBl);

    float acc[2][4][4];
    #pragma unroll
    for (int m = 0; m < 2; m++)
        #pragma unroll
        for (int n = 0; n < 4; n++)
            #pragma unroll
            for (int k = 0; k < 4; k++) acc[m][n][k] = 0.f;

    #pragma unroll 1
    for (int s = 0; s < 2; s++) {
        const __nv_bfloat16* Ah = s ? g_xhi : g_ahi;
        const __nv_bfloat16* Al = s ? g_xlo : g_alo;
        const __nv_bfloat16* Bh = g_wthi + (size_t)(layer * 2 + s) * DIM * DIM;
        const __nv_bfloat16* Bl = g_wtlo + (size_t)(layer * 2 + s) * DIM * DIM;

        #pragma unroll 1
        for (int kc = 0; kc < 2; kc++) {
            __syncthreads();
            copy_tile_a(sAh, Ah, row0, kc, tid);
            copy_tile_a(sAl, Al, row0, kc, tid);
            copy_tile_b(sBh, Bh, kc, tid);
            copy_tile_b(sBl, Bl, kc, tid);
            __syncthreads();

            #pragma unroll
            for (int k16 = 0; k16 < 4; k16++) {
                uint32_t h0, h1, h2, h3, h4, h5, h6, h7;
                uint32_t l0, l1, l2, l3, l4, l5, l6, l7;
                uint32_t p0, p1, p2, p3, p4, p5, p6, p7;
                uint32_t q0, q1, q2, q3, q4, q5, q6, q7;
                LDSM4(h0, h1, h2, h3, a_addr(uAh, wm * 32 +  0, k16, lane));
                LDSM4(h4, h5, h6, h7, a_addr(uAh, wm * 32 + 16, k16, lane));
                LDSM4(l0, l1, l2, l3, a_addr(uAl, wm * 32 +  0, k16, lane));
                LDSM4(l4, l5, l6, l7, a_addr(uAl, wm * 32 + 16, k16, lane));
                LDSM4(p0, p1, p2, p3, b_addr(uBh, wn * 32 +  0, k16, lane));
                LDSM4(p4, p5, p6, p7, b_addr(uBh, wn * 32 + 16, k16, lane));
                LDSM4(q0, q1, q2, q3, b_addr(uBl, wn * 32 +  0, k16, lane));
                LDSM4(q4, q5, q6, q7, b_addr(uBl, wn * 32 + 16, k16, lane));
                // Ah*Bh
                MMA16816(acc[0][0][0], acc[0][0][1], acc[0][0][2], acc[0][0][3], h0, h1, h2, h3, p0, p1);
                MMA16816(acc[0][1][0], acc[0][1][1], acc[0][1][2], acc[0][1][3], h0, h1, h2, h3, p2, p3);
                MMA16816(acc[0][2][0], acc[0][2][1], acc[0][2][2], acc[0][2][3], h0, h1, h2, h3, p4, p5);
                MMA16816(acc[0][3][0], acc[0][3][1], acc[0][3][2], acc[0][3][3], h0, h1, h2, h3, p6, p7);
                MMA16816(acc[1][0][0], acc[1][0][1], acc[1][0][2], acc[1][0][3], h4, h5, h6, h7, p0, p1);
                MMA16816(acc[1][1][0], acc[1][1][1], acc[1][1][2], acc[1][1][3], h4, h5, h6, h7, p2, p3);
                MMA16816(acc[1][2][0], acc[1][2][1], acc[1][2][2], acc[1][2][3], h4, h5, h6, h7, p4, p5);
                MMA16816(acc[1][3][0], acc[1][3][1], acc[1][3][2], acc[1][3][3], h4, h5, h6, h7, p6, p7);
                // Al*Bh
                MMA16816(acc[0][0][0], acc[0][0][1], acc[0][0][2], acc[0][0][3], l0, l1, l2, l3, p0, p1);
                MMA16816(acc[0][1][0], acc[0][1][1], acc[0][1][2], acc[0][1][3], l0, l1, l2, l3, p2, p3);
                MMA16816(acc[0][2][0], acc[0][2][1], acc[0][2][2], acc[0][2][3], l0, l1, l2, l3, p4, p5);
                MMA16816(acc[0][3][0], acc[0][3][1], acc[0][3][2], acc[0][3][3], l0, l1, l2, l3, p6, p7);
                MMA16816(acc[1][0][0], acc[1][0][1], acc[1][0][2], acc[1][0][3], l4, l5, l6, l7, p0, p1);
                MMA16816(acc[1][1][0], acc[1][1][1], acc[1][1][2], acc[1][1][3], l4, l5, l6, l7, p2, p3);
                MMA16816(acc[1][2][0], acc[1][2][1], acc[1][2][2], acc[1][2][3], l4, l5, l6, l7, p4, p5);
                MMA16816(acc[1][3][0], acc[1][3][1], acc[1][3][2], acc[1][3][3], l4, l5, l6, l7, p6, p7);
                // Ah*Bl
                MMA16816(acc[0][0][0], acc[0][0][1], acc[0][0][2], acc[0][0][3], h0, h1, h2, h3, q0, q1);
                MMA16816(acc[0][1][0], acc[0][1][1], acc[0][1][2], acc[0][1][3], h0, h1, h2, h3, q2, q3);
                MMA16816(acc[0][2][0], acc[0][2][1], acc[0][2][2], acc[0][2][3], h0, h1, h2, h3, q4, q5);
                MMA16816(acc[0][3][0], acc[0][3][1], acc[0][3][2], acc[0][3][3], h0, h1, h2, h3, q6, q7);
                MMA16816(acc[1][0][0], acc[1][0][1], acc[1][0][2], acc[1][0][3], h4, h5, h6, h7, q0, q1);
                MMA16816(acc[1][1][0], acc[1][1][1], acc[1][1][2], acc[1][1][3], h4, h5, h6, h7, q2, q3);
                MMA16816(acc[1][2][0], acc[1][2][1], acc[1][2][2], acc[1][2][3], h4, h5, h6, h7, q4, q5);
                MMA16816(acc[1][3][0], acc[1][3][1], acc[1][3][2], acc[1][3][3], h4, h5, h6, h7, q6, q7);
            }
        }
    }

    // epilogue: store y = acc + bias, accumulate BN column sums
    int gr = lane >> 2, t2 = (lane & 3) * 2;
    float s1[4][2], s2[4][2];
    #pragma unroll
    for (int n = 0; n < 4; n++) {
        s1[n][0] = 0.f; s1[n][1] = 0.f;
        s2[n][0] = 0.f; s2[n][1] = 0.f;
    }
    #pragma unroll
    for (int m = 0; m < 2; m++) {
        long r = row0 + wm * 32 + m * 16 + gr;
        bool v0 = r < N_NODES, v1 = (r + 8) < N_NODES;
        #pragma unroll
        for (int n = 0; n < 4; n++) {
            int c = wn * 32 + n * 8 + t2;
            float2 bb = *(const float2*)(bias + c);
            float a0 = acc[m][n][0] + bb.x, a1 = acc[m][n][1] + bb.y;
            float a2 = acc[m][n][2] + bb.x, a3 = acc[m][n][3] + bb.y;
            if (v0) {
                *(float2*)(g_y + r * DIM + c) = make_float2(a0, a1);
                s1[n][0] += a0; s2[n][0] += a0 * a0;
                s1[n][1] += a1; s2[n][1] += a1 * a1;
            }
            if (v1) {
                *(float2*)(g_y + (r + 8) * DIM + c) = make_float2(a2, a3);
                s1[n][0] += a2; s2[n][0] += a2 * a2;
                s1[n][1] += a3; s2[n][1] += a3 * a3;
            }
        }
    }
    #pragma unroll
    for (int x = 4; x <= 16; x <<= 1) {
        #pragma unroll
        for (int n = 0; n < 4; n++) {
            s1[n][0] += __shfl_xor_sync(0xffffffffu, s1[n][0], x);
            s1[n][1] += __shfl_xor_sync(0xffffffffu, s1[n][1], x);
            s2[n][0] += __shfl_xor_sync(0xffffffffu, s2[n][0], x);
            s2[n][1] += __shfl_xor_sync(0xffffffffu, s2[n][1], x);
        }
    }
    if (lane < 4) {
        #pragma unroll
        for (int n = 0; n < 4; n++) {
            int c = wn * 32 + n * 8 + lane * 2;
            atomicAdd(&g_sum[c],     s1[n][0]);
            atomicAdd(&g_sum[c + 1], s1[n][1]);
            atomicAdd(&g_sumsq[c],     s2[n][0]);
            atomicAdd(&g_sumsq[c + 1], s2[n][1]);
        }
    }
}

// ---------------- BN finalize (+ self-reset for next layer) ----------------
__global__ void bnfinal_kernel(const float* __restrict__ gamma,
                               const float* __restrict__ beta) {
    int j = threadIdx.x;
    if (j < DIM) {
        const float invN = 1.0f / (float)N_NODES;
        float mu = g_sum[j] * invN;
        float var = g_sumsq[j] * invN - mu * mu;
        float rs = rsqrtf(var + BN_EPS);
        float sc = rs * gamma[j];
        g_scale[j] = sc;
        g_shift[j] = beta[j] - mu * sc;
        g_sum[j] = 0.f;
        g_sumsq[j] = 0.f;
    }
}

// ---------------- normalize + ReLU -> xhi/xlo bf16 + xh fp16 (+ pool last) -----
__global__ void norm_kernel(const int* __restrict__ batch_ids, int write_x, int do_pool) {
    int q = blockIdx.x * blockDim.x + threadIdx.x;
    if (q >= N_NODES * (DIM / 4)) return;
    int row = q >> 5;
    int j4 = (q & 31) * 4;
    float4 v = *(const float4*)(g_y + (size_t)row * DIM + j4);
    float4 sc = *(const float4*)(g_scale + j4);
    float4 sh = *(const float4*)(g_shift + j4);
    v.x = fmaxf(fmaf(v.x, sc.x, sh.x), 0.f);
    v.y = fmaxf(fmaf(v.y, sc.y, sh.y), 0.f);
    v.z = fmaxf(fmaf(v.z, sc.z, sh.z), 0.f);
    v.w = fmaxf(fmaf(v.w, sc.w, sh.w), 0.f);
    if (write_x) {
        uint2 H, L;
        split4(v, H, L);
        *(uint2*)(g_xhi + (size_t)row * DIM + j4) = H;
        *(uint2*)(g_xlo + (size_t)row * DIM + j4) = L;
        *(uint2*)(g_xh + (size_t)row * DIM + j4) = pack_h4(v);
    }
    if (do_pool) {
        float* p = g_pooled + (size_t)batch_ids[row] * DIM + j4;
        atomicAdd(p + 0, v.x);
        atomicAdd(p + 1, v.y);
        atomicAdd(p + 2, v.z);
        atomicAdd(p + 3, v.w);
    }
}

// ---------------- MLP head: one block per graph ----------------
__global__ void head_kernel(const float* __restrict__ W1,
                            const float* __restrict__ b1,
                            const float* __restrict__ W2,
                            const float* __restrict__ b2,
                            float* __restrict__ out) {
    __shared__ float ph[DIM];
    __shared__ float h[HID];
    int g = blockIdx.x;
    int t = threadIdx.x;
    float invc = 1.0f / fmaxf((float)g_cnt[g], 1.0f);
    ph[t] = g_pooled[(size_t)g * DIM + t] * invc;
    __syncthreads();
    if (t < HID) {
        float acc = b1[t];
        #pragma unroll 4
        for (int k = 0; k < DIM; k++)
            acc += ph[k] * W1[k * HID + t];
        h[t] = fmaxf(acc, 0.f);
    }
    __syncthreads();
    if (t == 0) {
        float acc = b2[0];
        #pragma unroll
        for (int j = 0; j < HID; j++)
            acc += h[j] * W2[j];
        out[g] = acc;
    }
}

// ---------------- launch ----------------
extern "C" void kernel_launch(void* const* d_in, const int* in_sizes, int n_in,
                              void* d_out, int out_size) {
    const float* x     = (const float*)d_in[0];
    const float* Wl    = (const float*)d_in[1];
    const float* Wr    = (const float*)d_in[2];
    const float* b     = (const float*)d_in[3];
    const float* gamma = (const float*)d_in[4];
    const float* beta  = (const float*)d_in[5];
    const float* hW1   = (const float*)d_in[6];
    const float* hb1   = (const float*)d_in[7];
    const float* hW2   = (const float*)d_in[8];
    const float* hb2   = (const float*)d_in[9];
    const int* esrc    = (const int*)d_in[10];
    const int* edst    = (const int*)d_in[11];
    const int* bids    = (const int*)d_in[12];
    float* out = (float*)d_out;

    // --- graph structure + weight prep ---
    init_kernel<<<(N_GRAPHS * DIM + 255) / 256, 256>>>();
    deg_kernel<<<(N_EDGES + 255) / 256, 256>>>(edst);
    cnt_kernel<<<(N_NODES + 255) / 256, 256>>>(bids);
    scan1_kernel<<<N_SCAN_BLKS, SCAN_BLK>>>();
    scan2_kernel<<<1, 1>>>();
    scan3_kernel<<<(N_NODES + 255) / 256, 256>>>();
    csr_fill_kernel<<<(N_EDGES + 255) / 256, 256>>>(esrc, edst);
    wsplit_kernel<<<6, 256>>>(Wl, Wr);
    copy_x_kernel<<<(N_NODES * (DIM / 4) + 255) / 256, 256>>>(x);

    // --- 3 SAGE layers ---
    for (int l = 0; l < N_LAYERS; l++) {
        agg_kernel<<<(N_NODES * 32 + 255) / 256, 256>>>();
        gemm_mma_kernel<<<GEMM_TILES, 256>>>(l, b + (size_t)l * DIM);
        bnfinal_kernel<<<1, 128>>>(gamma + (size_t)l * DIM, beta + (size_t)l * DIM);
        norm_kernel<<<(N_NODES * (DIM / 4) + 255) / 256, 256>>>(
            bids, l < N_LAYERS - 1, l == N_LAYERS - 1);
    }

    // --- head ---
    head_kernel<<<N_GRAPHS, 128>>>(hW1, hb1, hW2, hb2, out);
}